// round 1
// baseline (speedup 1.0000x reference)
#include <cuda_runtime.h>
#include <cuda_bf16.h>

// ---------------------------------------------------------------------------
// Problem constants (fixed by setup_inputs)
// ---------------------------------------------------------------------------
#define NN 250000
#define EE 1000000
#define BB 500
#define FD 78

// ---------------------------------------------------------------------------
// Scratch (device globals: no allocation allowed)
// ---------------------------------------------------------------------------
__device__ float    g_bufA[NN * 156];        // 156 MB
__device__ float    g_bufB[NN * 156];        // 156 MB
__device__ float    g_dinv[NN];
__device__ int      g_cnt[NN];
__device__ int      g_rowptr[NN + 1];
__device__ int      g_cursor[NN];
__device__ int      g_csrc[EE];
__device__ int      g_bsum[512];
__device__ int      g_boff[512];
__device__ unsigned g_pool[BB * 312];
__device__ float    g_S1[BB * 1024];
__device__ float    g_S2[BB * 512];
__device__ float    g_xc[BB * 256];
__device__ float    g_G[BB * 256 * 26];      // [b][o*8+k][l]
__device__ float    g_Cbuf[BB * 3872];

// ---------------------------------------------------------------------------
// Small utility kernels
// ---------------------------------------------------------------------------
__global__ void k_zero_int(int* p, int n) {
    int i = blockIdx.x * blockDim.x + threadIdx.x;
    if (i < n) p[i] = 0;
}
__global__ void k_zero_u32(unsigned* p, int n) {
    int i = blockIdx.x * blockDim.x + threadIdx.x;
    if (i < n) p[i] = 0u;
}
__global__ void k_zero_f32(float* p, int n) {
    int i = blockIdx.x * blockDim.x + threadIdx.x;
    if (i < n) p[i] = 0.f;
}

// ---------------------------------------------------------------------------
// CSR build: count -> scan -> offsets -> fill
// ---------------------------------------------------------------------------
__global__ void k_count(const int* __restrict__ dst, int e) {
    int i = blockIdx.x * blockDim.x + threadIdx.x;
    if (i < e) atomicAdd(&g_cnt[dst[i]], 1);
}

__global__ void k_scan1(int n) {
    __shared__ int s[512];
    int t = threadIdx.x;
    int i = blockIdx.x * 512 + t;
    int v = (i < n) ? g_cnt[i] : 0;
    s[t] = v;
    __syncthreads();
    for (int off = 1; off < 512; off <<= 1) {
        int tmp = (t >= off) ? s[t - off] : 0;
        __syncthreads();
        s[t] += tmp;
        __syncthreads();
    }
    if (i < n) g_rowptr[i] = s[t] - v;   // exclusive within block
    if (t == 511) g_bsum[blockIdx.x] = s[511];
}

__global__ void k_scan2(int nb) {
    __shared__ int s[512];
    int t = threadIdx.x;
    int v = (t < nb) ? g_bsum[t] : 0;
    s[t] = v;
    __syncthreads();
    for (int off = 1; off < 512; off <<= 1) {
        int tmp = (t >= off) ? s[t - off] : 0;
        __syncthreads();
        s[t] += tmp;
        __syncthreads();
    }
    if (t < nb) g_boff[t] = s[t] - v;    // exclusive
}

__global__ void k_scan3(int n, int e) {
    int i = blockIdx.x * blockDim.x + threadIdx.x;
    if (i < n) {
        int v = g_rowptr[i] + g_boff[i >> 9];
        g_rowptr[i] = v;
        g_cursor[i] = v;
        g_dinv[i] = rsqrtf((float)g_cnt[i] + 1.0f);   // degree + self-loop
    }
    if (i == 0) g_rowptr[n] = e;
}

__global__ void k_fill(const int* __restrict__ src, const int* __restrict__ dst, int e) {
    int i = blockIdx.x * blockDim.x + threadIdx.x;
    if (i < e) {
        int d = dst[i];
        int p = atomicAdd(&g_cursor[d], 1);
        g_csrc[p] = src[i];
    }
}

// ---------------------------------------------------------------------------
// Aggregation: out[v] = dinv[v] * ( s(v)*in[v] + sum_{u in N(v)} s(u)*in[u] )
// PRESCALED: input rows already carry their dinv factor (s == 1)
// One warp per node; F columns strided over lanes.
// ---------------------------------------------------------------------------
template <int F, bool PRESCALED>
__global__ void k_agg(const float* __restrict__ in, float* __restrict__ out, int n) {
    int warp = (blockIdx.x * blockDim.x + threadIdx.x) >> 5;
    int lane = threadIdx.x & 31;
    if (warp >= n) return;
    const int v = warp;
    constexpr int R = (F + 31) / 32;
    float dv = g_dinv[v];
    float ss = PRESCALED ? 1.f : dv;
    float acc[R];
#pragma unroll
    for (int i = 0; i < R; i++) {
        int f = lane + 32 * i;
        acc[i] = (f < F) ? in[(size_t)v * F + f] * ss : 0.f;
    }
    int e0 = g_rowptr[v], e1 = g_rowptr[v + 1];
    for (int e = e0; e < e1; e++) {
        int u = g_csrc[e];
        float us = PRESCALED ? 1.f : g_dinv[u];
#pragma unroll
        for (int i = 0; i < R; i++) {
            int f = lane + 32 * i;
            if (f < F) acc[i] += in[(size_t)u * F + f] * us;
        }
    }
#pragma unroll
    for (int i = 0; i < R; i++) {
        int f = lane + 32 * i;
        if (f < F) out[(size_t)v * F + f] = acc[i] * dv;
    }
}

// ---------------------------------------------------------------------------
// Generic f32 SIMT GEMM: C[NR,M] = A[NR,K] @ W[K,M]   (all row-major)
// BM=128, BN=64, BK=16, 256 threads, 8x4 per-thread microtile.
// Epilogues:
//  0 STORE      : C = acc + bias
//  1 RELU       : C = relu(acc + bias)
//  2 RELU_DINV  : C = relu(acc + bias) * dinv[row]
//  3 MAXPOOL    : atomicMax(pool[batch[row]*M + col], bits(relu(acc+bias)))
//  4 ADD_ATOMIC : atomicAdd(C, acc + (z==0 ? bias : 0))   (split-K)
// ---------------------------------------------------------------------------
#define GBM 128
#define GBN 64
#define GBK 16

template <int EPI>
__global__ __launch_bounds__(256)
void k_gemm(const float* __restrict__ A, int lda,
            const float* __restrict__ W, int ldb,
            float* __restrict__ C, int ldc,
            int NR, int M, int K,
            const float* __restrict__ bias,
            const float* __restrict__ dinv,
            const int* __restrict__ batch,
            unsigned* __restrict__ pool,
            int kChunk) {
    __shared__ float As[GBK][GBM + 4];
    __shared__ float Bs[GBK][GBN + 4];

    const int m0 = blockIdx.x * GBM;
    const int n0 = blockIdx.y * GBN;
    const int kb = blockIdx.z * kChunk;
    const int ke = min(K, kb + kChunk);

    const int tid = threadIdx.x;
    const int tN = tid & 15;   // 16 col groups
    const int tM = tid >> 4;   // 16 row groups

    float acc[8][4];
#pragma unroll
    for (int i = 0; i < 8; i++)
#pragma unroll
        for (int j = 0; j < 4; j++) acc[i][j] = 0.f;

    for (int k0 = kb; k0 < ke; k0 += GBK) {
#pragma unroll
        for (int r = 0; r < 8; r++) {
            int idx = tid + r * 256;
            int mm = idx >> 4, kk = idx & 15;
            int gm = m0 + mm, gk = k0 + kk;
            As[kk][mm] = (gm < NR && gk < ke) ? A[(size_t)gm * lda + gk] : 0.f;
        }
#pragma unroll
        for (int r = 0; r < 4; r++) {
            int idx = tid + r * 256;
            int kk = idx >> 6, nn = idx & 63;
            int gk = k0 + kk, gn = n0 + nn;
            Bs[kk][nn] = (gk < ke && gn < M) ? W[(size_t)gk * ldb + gn] : 0.f;
        }
        __syncthreads();
#pragma unroll
        for (int kk = 0; kk < GBK; kk++) {
            float4 a0 = *reinterpret_cast<const float4*>(&As[kk][tM * 8]);
            float4 a1 = *reinterpret_cast<const float4*>(&As[kk][tM * 8 + 4]);
            float4 b0 = *reinterpret_cast<const float4*>(&Bs[kk][tN * 4]);
            float a[8] = {a0.x, a0.y, a0.z, a0.w, a1.x, a1.y, a1.z, a1.w};
            float b[4] = {b0.x, b0.y, b0.z, b0.w};
#pragma unroll
            for (int i = 0; i < 8; i++)
#pragma unroll
                for (int j = 0; j < 4; j++)
                    acc[i][j] = fmaf(a[i], b[j], acc[i][j]);
        }
        __syncthreads();
    }

#pragma unroll
    for (int i = 0; i < 8; i++) {
        int row = m0 + tM * 8 + i;
        if (row >= NR) continue;
#pragma unroll
        for (int j = 0; j < 4; j++) {
            int col = n0 + tN * 4 + j;
            if (col >= M) continue;
            float v = acc[i][j];
            if (EPI == 0) {
                if (bias) v += bias[col];
                C[(size_t)row * ldc + col] = v;
            } else if (EPI == 1) {
                v += bias[col];
                C[(size_t)row * ldc + col] = fmaxf(v, 0.f);
            } else if (EPI == 2) {
                v += bias[col];
                C[(size_t)row * ldc + col] = fmaxf(v, 0.f) * dinv[row];
            } else if (EPI == 3) {
                v = fmaxf(v + bias[col], 0.f);
                atomicMax(&pool[(size_t)batch[row] * M + col], __float_as_uint(v));
            } else {  // 4
                if (blockIdx.z == 0 && bias) v += bias[col];
                atomicAdd(&C[(size_t)row * ldc + col], v);
            }
        }
    }
}

// ---------------------------------------------------------------------------
// Protein branch: G[b,o,k,l] = sum_i conv_w[o,i,k] * [target[b,i] == l]
// One block per graph, 256 threads = (o,k) pairs, private 26-bin shared accs.
// ---------------------------------------------------------------------------
__global__ void k_gbuild(const int* __restrict__ target, const float* __restrict__ conv_w) {
    __shared__ int   ts[1000];
    __shared__ float acc[256 * 26];
    const int b = blockIdx.x, tid = threadIdx.x;
    for (int i = tid; i < 1000; i += 256) ts[i] = target[b * 1000 + i];
#pragma unroll
    for (int l = 0; l < 26; l++) acc[tid * 26 + l] = 0.f;
    __syncthreads();
    const int o = tid >> 3, k = tid & 7;
    const float* wp = conv_w + o * 8000 + k;
    for (int i = 0; i < 1000; i++) {
        acc[tid * 26 + ts[i]] += wp[i * 8];
    }
    float* g = g_G + (size_t)b * 6656 + tid * 26;
#pragma unroll
    for (int l = 0; l < 26; l++) g[l] = acc[tid * 26 + l];
}

// c[b,o,h] = conv_b[o] + sum_{k,l} G[b,o,k,l] * emb[l, h+k]
__global__ void k_cconv(const float* __restrict__ emb, const float* __restrict__ conv_b) {
    __shared__ float Gs[6656];
    __shared__ float Es[26 * 128];
    const int b = blockIdx.x, tid = threadIdx.x;
    for (int i = tid; i < 6656; i += 256) Gs[i] = g_G[(size_t)b * 6656 + i];
    for (int i = tid; i < 26 * 128; i += 256) Es[i] = emb[i];
    __syncthreads();
    for (int idx = tid; idx < 3872; idx += 256) {
        int o = idx / 121, h = idx % 121;
        float s = conv_b[o];
#pragma unroll
        for (int k = 0; k < 8; k++)
#pragma unroll
            for (int l = 0; l < 26; l++)
                s += Gs[(o * 8 + k) * 26 + l] * Es[l * 128 + h + k];
        g_Cbuf[(size_t)b * 3872 + idx] = s;
    }
}

// ---------------------------------------------------------------------------
// Final projection: out[r] = dot(S2[r,:512], out_w) + out_b. One warp per row.
// ---------------------------------------------------------------------------
__global__ void k_out(const float* __restrict__ ow, const float* __restrict__ ob,
                      float* __restrict__ out, int rows) {
    int row = blockIdx.x * 8 + (threadIdx.x >> 5);
    int lane = threadIdx.x & 31;
    if (row >= rows) return;
    float s = 0.f;
    for (int j = lane; j < 512; j += 32) s += g_S2[row * 512 + j] * ow[j];
#pragma unroll
    for (int off = 16; off; off >>= 1) s += __shfl_down_sync(0xffffffffu, s, off);
    if (lane == 0) out[row] = s + ob[0];
}

// ---------------------------------------------------------------------------
// Launch
// ---------------------------------------------------------------------------
extern "C" void kernel_launch(void* const* d_in, const int* in_sizes, int n_in,
                              void* d_out, int out_size) {
    const float* x       = (const float*)d_in[0];
    const int*   ei      = (const int*)d_in[1];      // [2, E]: row0 src, row1 dst
    const int*   batch   = (const int*)d_in[2];
    const int*   target  = (const int*)d_in[3];
    const float* W1      = (const float*)d_in[4];
    const float* b1      = (const float*)d_in[5];
    const float* W2      = (const float*)d_in[6];
    const float* b2      = (const float*)d_in[7];
    const float* W3      = (const float*)d_in[8];
    const float* b3      = (const float*)d_in[9];
    const float* fcg1_w  = (const float*)d_in[10];
    const float* fcg1_b  = (const float*)d_in[11];
    const float* fcg2_w  = (const float*)d_in[12];
    const float* fcg2_b  = (const float*)d_in[13];
    const float* emb     = (const float*)d_in[14];
    const float* conv_w  = (const float*)d_in[15];
    const float* conv_b  = (const float*)d_in[16];
    const float* fcxt_w  = (const float*)d_in[17];
    const float* fcxt_b  = (const float*)d_in[18];
    const float* fc1_w   = (const float*)d_in[19];
    const float* fc1_b   = (const float*)d_in[20];
    const float* fc2_w   = (const float*)d_in[21];
    const float* fc2_b   = (const float*)d_in[22];
    const float* out_w   = (const float*)d_in[23];
    const float* out_b   = (const float*)d_in[24];
    float* out = (float*)d_out;

    float *bufA, *bufB, *dinv, *S1, *S2, *xc, *Cbuf;
    int *cnt;
    unsigned* pool;
    cudaGetSymbolAddress((void**)&bufA, g_bufA);
    cudaGetSymbolAddress((void**)&bufB, g_bufB);
    cudaGetSymbolAddress((void**)&dinv, g_dinv);
    cudaGetSymbolAddress((void**)&cnt,  g_cnt);
    cudaGetSymbolAddress((void**)&pool, g_pool);
    cudaGetSymbolAddress((void**)&S1,   g_S1);
    cudaGetSymbolAddress((void**)&S2,   g_S2);
    cudaGetSymbolAddress((void**)&xc,   g_xc);
    cudaGetSymbolAddress((void**)&Cbuf, g_Cbuf);

    const int N = NN, E = EE, B = BB;
    const int NB = (N + 511) / 512;               // 489 scan blocks
    const int MG = (N + GBM - 1) / GBM;           // 1954 row blocks

    // ---- CSR + dinv ----
    k_zero_int<<<(N + 255) / 256, 256>>>(cnt, N);
    k_count<<<(E + 255) / 256, 256>>>(ei + E, E);
    k_scan1<<<NB, 512>>>(N);
    k_scan2<<<1, 512>>>(NB);
    k_scan3<<<(N + 255) / 256, 256>>>(N, E);
    k_fill<<<(E + 255) / 256, 256>>>(ei, ei + E, E);

    // ---- GCN layers (aggregate-then-GEMM) ----
    k_agg<78, false><<<N / 8, 256>>>(x, bufA, N);
    k_gemm<2><<<dim3(MG, 2), 256>>>(bufA, 78, W1, 78, bufB, 78, N, 78, 78,
                                    b1, dinv, nullptr, nullptr, 78);
    k_agg<78, true><<<N / 8, 256>>>(bufB, bufA, N);
    k_gemm<2><<<dim3(MG, 3), 256>>>(bufA, 78, W2, 156, bufB, 156, N, 156, 78,
                                    b2, dinv, nullptr, nullptr, 78);
    k_agg<156, true><<<N / 8, 256>>>(bufB, bufA, N);
    k_zero_u32<<<(B * 312 + 255) / 256, 256>>>(pool, B * 312);
    k_gemm<3><<<dim3(MG, 5), 256>>>(bufA, 156, W3, 312, nullptr, 312, N, 312, 156,
                                    b3, nullptr, batch, pool, 156);

    // ---- graph head ----
    k_gemm<1><<<dim3(4, 16), 256>>>((const float*)pool, 312, fcg1_w, 1024, S1, 1024,
                                    B, 1024, 312, fcg1_b, nullptr, nullptr, nullptr, 312);
    k_zero_f32<<<(B * 256 + 255) / 256, 256>>>(xc, B * 256);
    k_gemm<0><<<dim3(4, 2), 256>>>(S1, 1024, fcg2_w, 128, xc, 256,
                                   B, 128, 1024, fcg2_b, nullptr, nullptr, nullptr, 1024);

    // ---- protein branch (alphabet-factored conv) ----
    k_gbuild<<<B, 256>>>(target, conv_w);
    k_cconv<<<B, 256>>>(emb, conv_b);
    k_gemm<4><<<dim3(4, 2, 16), 256>>>(Cbuf, 3872, fcxt_w, 128, xc + 128, 256,
                                       B, 128, 3872, fcxt_b, nullptr, nullptr, nullptr, 242);

    // ---- fusion head ----
    k_gemm<1><<<dim3(4, 16), 256>>>(xc, 256, fc1_w, 1024, S1, 1024,
                                    B, 1024, 256, fc1_b, nullptr, nullptr, nullptr, 256);
    k_gemm<1><<<dim3(4, 8), 256>>>(S1, 1024, fc2_w, 512, S2, 512,
                                   B, 512, 1024, fc2_b, nullptr, nullptr, nullptr, 1024);
    k_out<<<(B + 7) / 8, 256>>>(out_w, out_b, out, B);
}